// round 14
// baseline (speedup 1.0000x reference)
#include <cuda_runtime.h>
#include <math.h>
#include <float.h>

#define BATCH 8
#define NPTS  4096
#define KN    10
#define NNB   9
#define PI_F  3.14159265358979323846f
#define INF_F __int_as_float(0x7f800000)

// scratch: neighbor indices (B, N, 9)
__device__ int g_knn_idx[BATCH * NPTS * NNB];

// packed f32x2 fma (sm_103a): per-lane fp32 FMA, bit-identical to scalar fmaf
#define FMA2(out, a, b, c) \
    asm("fma.rn.f32x2 %0, %1, %2, %3;" : "=l"(out) : "l"(a), "l"(b), "l"(c))
#define UNPACK2(lo, hi, v) \
    asm("mov.b64 {%0, %1}, %2;" : "=f"(lo), "=f"(hi) : "l"(v))
#define PACK2(out, lo, hi) \
    asm("mov.b64 %0, {%1, %2};" : "=l"(out) : "f"(lo), "f"(hi))

// ---------------------------------------------------------------------------
// insert: unsorted top-10, replace (first) slot equal to running max.
// parallel prefix-OR first-match + FMNMX tree. (proven exact, rounds 3-13)
// ---------------------------------------------------------------------------
#define KNN_INSERT(e, c)                                                     \
    if ((e) < mx) {                                                          \
        bool m0 = (bd[0] == mx), m1 = (bd[1] == mx);                         \
        bool m2 = (bd[2] == mx), m3 = (bd[3] == mx);                         \
        bool m4 = (bd[4] == mx), m5 = (bd[5] == mx);                         \
        bool m6 = (bd[6] == mx), m7 = (bd[7] == mx);                         \
        bool m8 = (bd[8] == mx), m9 = (bd[9] == mx);                         \
        bool o01 = m0 | m1, o23 = m2 | m3, o45 = m4 | m5, o67 = m6 | m7;     \
        bool o03 = o01 | o23, o07 = o03 | o45 | o67;                         \
        if (m0)                      { bd[0] = (e); bi[0] = (c); }           \
        if (m1 & !m0)                { bd[1] = (e); bi[1] = (c); }           \
        if (m2 & !o01)               { bd[2] = (e); bi[2] = (c); }           \
        if (m3 & !(o01 | m2))        { bd[3] = (e); bi[3] = (c); }           \
        if (m4 & !o03)               { bd[4] = (e); bi[4] = (c); }           \
        if (m5 & !(o03 | m4))        { bd[5] = (e); bi[5] = (c); }           \
        if (m6 & !(o03 | o45))       { bd[6] = (e); bi[6] = (c); }           \
        if (m7 & !(o03 | o45 | m6))  { bd[7] = (e); bi[7] = (c); }           \
        if (m8 & !o07)               { bd[8] = (e); bi[8] = (c); }           \
        if (m9 & !(o07 | m8))        { bd[9] = (e); bi[9] = (c); }           \
        float x0 = fmaxf(bd[0], bd[1]);                                      \
        float x1 = fmaxf(bd[2], bd[3]);                                      \
        float x2 = fmaxf(bd[4], bd[5]);                                      \
        float x3 = fmaxf(bd[6], bd[7]);                                      \
        float x4 = fmaxf(bd[8], bd[9]);                                      \
        mx = fmaxf(fmaxf(fmaxf(x0, x1), fmaxf(x2, x3)), x4);                 \
    }

// parallel-prefix 4-way append: independent predicated STS, 2-deep IADD tree
#define KNN_APPEND4(e0_, e1_, e2_, e3_, c0_, c1_, c2_, c3_)                  \
    {                                                                        \
        bool t0_ = (e0_) < mx, t1_ = (e1_) < mx;                             \
        bool t2_ = (e2_) < mx, t3_ = (e3_) < mx;                             \
        int s01_ = (int)t0_ + (int)t1_;                                      \
        int q0_ = cnt;                                                       \
        int q1_ = cnt + (int)t0_;                                            \
        int q2_ = cnt + s01_;                                                \
        int q3_ = q2_ + (int)t2_;                                            \
        if (t0_) sstk[q0_ * 512 + tid] = make_float2((e0_), __int_as_float(c0_)); \
        if (t1_) sstk[q1_ * 512 + tid] = make_float2((e1_), __int_as_float(c1_)); \
        if (t2_) sstk[q2_ * 512 + tid] = make_float2((e2_), __int_as_float(c2_)); \
        if (t3_) sstk[q3_ * 512 + tid] = make_float2((e3_), __int_as_float(c3_)); \
        cnt = q3_ + (int)t3_;                                                \
    }

// drain this thread's stack through the exact insert
#define KNN_DRAIN()                                                          \
    {                                                                        \
        for (int j = 0; j < cnt; ++j) {                                      \
            float2 v = sstk[j * 512 + tid];                                  \
            float de = v.x;                                                  \
            int   dc = __float_as_int(v.y);                                  \
            KNN_INSERT(de, dc);                                              \
        }                                                                    \
        cnt = 0;                                                             \
    }

// evaluate 4 candidates (2 packed pairs at pair index pp) and append
#define KNN_EVAL4P(pp)                                                       \
    {                                                                        \
        ulonglong2 A0 = sptA[(pp)];                                          \
        ulonglong2 B0 = sptB[(pp)];                                          \
        ulonglong2 A1 = sptA[(pp) + 1];                                      \
        ulonglong2 B1 = sptB[(pp) + 1];                                      \
        unsigned long long u0_, u1_;                                         \
        FMA2(u0_, nqz2, B0.x, B0.y);                                         \
        FMA2(u0_, nqy2, A0.y, u0_);                                          \
        FMA2(u0_, nqx2, A0.x, u0_);                                          \
        FMA2(u1_, nqz2, B1.x, B1.y);                                         \
        FMA2(u1_, nqy2, A1.y, u1_);                                          \
        FMA2(u1_, nqx2, A1.x, u1_);                                          \
        float e0_, e1_, e2_, e3_;                                            \
        UNPACK2(e0_, e1_, u0_);                                              \
        UNPACK2(e2_, e3_, u1_);                                              \
        KNN_APPEND4(e0_, e1_, e2_, e3_,                                      \
                    2 * (pp), 2 * (pp) + 1, 2 * (pp) + 2, 2 * (pp) + 3);     \
    }

// ---------------------------------------------------------------------------
// Kernel 1: brute-force kNN. 4 threads per query (1024 candidates each),
// 512-thread blocks, 256 blocks -> 2 blocks/SM co-resident (~7 warps/SMSP).
// Pair-packed SMEM + f32x2 FMA, prefix appends, vote every 8 cands,
// 12-deep stacks (48 KB). Exact 4-way merge; drop self (= global min).
// SMEM: A pairs 32KB | B pairs 32KB | stacks 48KB = 112KB (2 blocks = 224KB)
// ---------------------------------------------------------------------------
__global__ void __launch_bounds__(512, 2) knn_kernel(const float* __restrict__ x)
{
    extern __shared__ char dsm[];
    ulonglong2* sptA = (ulonglong2*)dsm;             // 32 KB: 2048 pairs
    ulonglong2* sptB = (ulonglong2*)(dsm + 32768);   // 32 KB
    float2*     sstk = (float2*)(dsm + 65536);       // 48 KB: 12-deep stacks

    const int b  = blockIdx.x >> 5;              // 32 blocks per batch
    const int q0 = (blockIdx.x & 31) << 7;       // 128 queries per block
    const float* xb = x + b * 3 * NPTS;
    const int tid = threadIdx.x;

    {
        float* Af = (float*)dsm;
        float* Bf = (float*)(dsm + 32768);
        for (int i = tid; i < NPTS; i += 512) {
            float px = xb[i];
            float py = xb[NPTS + i];
            float pz = xb[2 * NPTS + i];
            float pw = 0.5f * (px * px + py * py + pz * pz);
            int pi = i >> 1, lo = i & 1;
            Af[pi * 4 + lo]     = px;
            Af[pi * 4 + 2 + lo] = py;
            Bf[pi * 4 + lo]     = pz;
            Bf[pi * 4 + 2 + lo] = pw;
        }
    }
    __syncthreads();

    const int sub = tid >> 7;          // 0..3 : candidate quarter
    const int ql  = tid & 127;         // local query
    const int q   = q0 + ql;
    const int p0  = sub << 9;          // sub * 512 pairs (1024 candidates)

    // query coords from global (coalesced within warp)
    const float qx = xb[q], qy = xb[NPTS + q], qz = xb[2 * NPTS + q];
    const float nqx = -qx, nqy = -qy, nqz = -qz;
    unsigned long long nqx2, nqy2, nqz2;
    PACK2(nqx2, nqx, nqx);
    PACK2(nqy2, nqy, nqy);
    PACK2(nqz2, nqz, nqz);

    float bd[KN];
    int   bi[KN];
#pragma unroll
    for (int s = 0; s < KN; ++s) { bd[s] = INF_F; bi[s] = 0; }
    float mx = INF_F;
    int cnt = 0;

#pragma unroll 1
    for (int pp = p0; pp < p0 + 512; pp += 4) {   // 4 pairs = 8 candidates
        KNN_EVAL4P(pp);
        KNN_EVAL4P(pp + 2);
        if (__any_sync(0xffffffffu, cnt >= 5)) {
            KNN_DRAIN();
        }
    }
    KNN_DRAIN();

    // --- exact 4-way merge of partial lists (reuse point region) ---
    __syncthreads();
    float* pd = (float*)dsm;                    // 512*10 floats = 20 KB
    int*   pi = (int*)(pd + 512 * KN);          // 512*10 ints   = 20 KB

    const int base = (ql * 4 + sub) * KN;
#pragma unroll
    for (int s = 0; s < KN; ++s) { pd[base + s] = bd[s]; pi[base + s] = bi[s]; }
    __syncthreads();

    if (sub == 0) {
#pragma unroll 1
        for (int t = 1; t < 4; ++t) {
            const int ob = (ql * 4 + t) * KN;
#pragma unroll
            for (int s = 0; s < KN; ++s) {
                float e = pd[ob + s];
                int   c = pi[ob + s];
                KNN_INSERT(e, c);
            }
        }

        // self = strict global min; emit the other 9 (order arbitrary)
        float mn = bd[0]; int ms = 0;
#pragma unroll
        for (int s = 1; s < KN; ++s) {
            if (bd[s] < mn) { mn = bd[s]; ms = s; }
        }
        int* outp = g_knn_idx + (b * NPTS + q) * NNB;
        int k = 0;
#pragma unroll
        for (int s = 0; s < KN; ++s) {
            if (s != ms) { outp[k] = bi[s]; ++k; }
        }
    }
}

// ---------------------------------------------------------------------------
// Kernel 2: umbrella features + fused MLP (BN folded). One thread per (b,n).
// (no reg cap: 255 regs, no spills — measured ~25us)
// ---------------------------------------------------------------------------
__global__ void __launch_bounds__(256) feat_kernel(
    const float* __restrict__ x,
    const float* __restrict__ conv1_w,
    const float* __restrict__ bn1_g, const float* __restrict__ bn1_b,
    const float* __restrict__ bn1_m, const float* __restrict__ bn1_v,
    const float* __restrict__ conv2_w, const float* __restrict__ conv2_b,
    const float* __restrict__ bn2_g, const float* __restrict__ bn2_b,
    const float* __restrict__ bn2_m, const float* __restrict__ bn2_v,
    const float* __restrict__ conv3_w, const float* __restrict__ conv3_b,
    float* __restrict__ out)
{
    extern __shared__ float4 spts[];
    __shared__ float W1f[81], W2f[81], W3s[81];
    __shared__ float b1f[9], b2f[9], b3f[9];

    const int b  = blockIdx.x >> 4;
    const int n0 = (blockIdx.x & 15) * 256;
    const int tid = threadIdx.x;

    if (tid < 81) {
        int o = tid / 9;
        float i1 = bn1_g[o] * rsqrtf(bn1_v[o] + 1e-5f);
        float i2 = bn2_g[o] * rsqrtf(bn2_v[o] + 1e-5f);
        W1f[tid] = conv1_w[tid] * i1;
        W2f[tid] = conv2_w[tid] * i2;
        W3s[tid] = conv3_w[tid];
        if (tid < 9) {
            float j1 = bn1_g[tid] * rsqrtf(bn1_v[tid] + 1e-5f);
            float j2 = bn2_g[tid] * rsqrtf(bn2_v[tid] + 1e-5f);
            b1f[tid] = bn1_b[tid] - bn1_m[tid] * j1;
            b2f[tid] = conv2_b[tid] * j2 + bn2_b[tid] - bn2_m[tid] * j2;
            b3f[tid] = conv3_b[tid];
        }
    }

    const float* xb = x + b * 3 * NPTS;
    for (int i = tid; i < NPTS; i += blockDim.x) {
        spts[i] = make_float4(xb[i], xb[NPTS + i], xb[2 * NPTS + i], 0.0f);
    }
    __syncthreads();

    const int n = n0 + tid;
    float4 p = spts[n];

    float gx[NNB], gy[NNB], gz[NNB], ph[NNB];
    const int* nb = g_knn_idx + (b * NPTS + n) * NNB;
#pragma unroll
    for (int j = 0; j < NNB; ++j) {
        float4 pp = spts[nb[j]];
        gx[j] = pp.x - p.x;
        gy[j] = pp.y - p.y;
        gz[j] = pp.z - p.z;
        ph[j] = atan2f(gy[j], gx[j]);
    }

#pragma unroll 1
    for (int a = 1; a < NNB; ++a) {
        float kp = ph[a], kx = gx[a], ky = gy[a], kz = gz[a];
        int t = a - 1;
        while (t >= 0 && ph[t] > kp) {
            ph[t + 1] = ph[t]; gx[t + 1] = gx[t]; gy[t + 1] = gy[t]; gz[t + 1] = gz[t];
            --t;
        }
        ph[t + 1] = kp; gx[t + 1] = kx; gy[t + 1] = ky; gz[t + 1] = kz;
    }

    float acc[9];
#pragma unroll
    for (int o = 0; o < 9; ++o) acc[o] = 0.0f;

    float pos = 1.0f;

#pragma unroll 1
    for (int j = 0; j < NNB; ++j) {
        int jn = (j + 1 == NNB) ? 0 : j + 1;
        float sx = gx[j],  sy = gy[j],  sz = gz[j];
        float rx = gx[jn], ry = gy[jn], rz = gz[jn];

        float cxv = sy * rz - sz * ry;
        float cyv = sz * rx - sx * rz;
        float czv = sx * ry - sy * rx;
        float nrm = sqrtf(cxv * cxv + cyv * cyv + czv * czv);
        float inn = 1.0f / fmaxf(nrm, 1e-10f);
        float ux = cxv * inn, uy = cyv * inn, uz = czv * inn;
        if (j == 0) pos = (ux > 0.0f) ? 1.0f : -1.0f;
        float nx = ux * pos, ny = uy * pos, nz = uz * pos;
        nx = isnan(nx) ? 0.0f : nx;
        ny = isnan(ny) ? 0.0f : ny;
        nz = isnan(nz) ? 0.0f : nz;

        float ccx = (sx + rx) * (1.0f / 3.0f);
        float ccy = (sy + ry) * (1.0f / 3.0f);
        float ccz = (sz + rz) * (1.0f / 3.0f);
        float rho = sqrtf(ccx * ccx + ccy * ccy + ccz * ccz);
        float ct  = ccz / fmaxf(rho, 1e-8f);
        ct = fminf(fmaxf(ct, -1.0f), 1.0f);
        float th  = acosf(ct) * (1.0f / PI_F);
        float phc = atan2f(ccy, ccx) * (1.0f / (2.0f * PI_F)) + 0.5f;

        float f[9] = { ccx, ccy, ccz, rho, th, phc, nx, ny, nz };

        float h1v[9];
#pragma unroll
        for (int o = 0; o < 9; ++o) {
            float a = b1f[o];
#pragma unroll
            for (int c = 0; c < 9; ++c) a = fmaf(W1f[o * 9 + c], f[c], a);
            h1v[o] = fmaxf(a, 0.0f);
        }
        float h2v[9];
#pragma unroll
        for (int o = 0; o < 9; ++o) {
            float a = b2f[o];
#pragma unroll
            for (int c = 0; c < 9; ++c) a = fmaf(W2f[o * 9 + c], h1v[c], a);
            h2v[o] = fmaxf(a, 0.0f);
        }
#pragma unroll
        for (int o = 0; o < 9; ++o) {
            float a = b3f[o];
#pragma unroll
            for (int c = 0; c < 9; ++c) a = fmaf(W3s[o * 9 + c], h2v[c], a);
            acc[o] += a;
        }
    }

    float* ob = out + b * 9 * NPTS + n;
#pragma unroll
    for (int o = 0; o < 9; ++o) ob[o * NPTS] = acc[o];
}

// ---------------------------------------------------------------------------
extern "C" void kernel_launch(void* const* d_in, const int* in_sizes, int n_in,
                              void* d_out, int out_size)
{
    const float* x       = (const float*)d_in[0];
    const float* conv1_w = (const float*)d_in[1];
    const float* bn1_g   = (const float*)d_in[2];
    const float* bn1_b   = (const float*)d_in[3];
    const float* bn1_m   = (const float*)d_in[4];
    const float* bn1_v   = (const float*)d_in[5];
    const float* conv2_w = (const float*)d_in[6];
    const float* conv2_b = (const float*)d_in[7];
    const float* bn2_g   = (const float*)d_in[8];
    const float* bn2_b   = (const float*)d_in[9];
    const float* bn2_m   = (const float*)d_in[10];
    const float* bn2_v   = (const float*)d_in[11];
    const float* conv3_w = (const float*)d_in[12];
    const float* conv3_b = (const float*)d_in[13];
    float* out = (float*)d_out;

    const int smem_knn  = 65536 + 49152;              // 112 KB
    const int smem_feat = NPTS * (int)sizeof(float4); // 64 KB
    cudaFuncSetAttribute(knn_kernel,  cudaFuncAttributeMaxDynamicSharedMemorySize, smem_knn);
    cudaFuncSetAttribute(feat_kernel, cudaFuncAttributeMaxDynamicSharedMemorySize, smem_feat);

    knn_kernel<<<BATCH * 32, 512, smem_knn>>>(x);
    feat_kernel<<<BATCH * (NPTS / 256), 256, smem_feat>>>(
        x, conv1_w, bn1_g, bn1_b, bn1_m, bn1_v,
        conv2_w, conv2_b, bn2_g, bn2_b, bn2_m, bn2_v,
        conv3_w, conv3_b, out);
}

// round 15
// speedup vs baseline: 1.0121x; 1.0121x over previous
#include <cuda_runtime.h>
#include <math.h>
#include <float.h>

#define BATCH 8
#define NPTS  4096
#define KN    10
#define NNB   9
#define PI_F  3.14159265358979323846f
#define INF_F __int_as_float(0x7f800000)

// scratch: neighbor indices (B, N, 9)
__device__ int g_knn_idx[BATCH * NPTS * NNB];

// packed f32x2 fma (sm_103a): per-lane fp32 FMA, bit-identical to scalar fmaf
#define FMA2(out, a, b, c) \
    asm("fma.rn.f32x2 %0, %1, %2, %3;" : "=l"(out) : "l"(a), "l"(b), "l"(c))
#define UNPACK2(lo, hi, v) \
    asm("mov.b64 {%0, %1}, %2;" : "=f"(lo), "=f"(hi) : "l"(v))
#define PACK2(out, lo, hi) \
    asm("mov.b64 %0, {%1, %2};" : "=l"(out) : "f"(lo), "f"(hi))

// ---------------------------------------------------------------------------
// insert: unsorted top-10, replace (first) slot equal to running max.
// parallel prefix-OR first-match + FMNMX tree. (proven exact, rounds 3-14)
// ---------------------------------------------------------------------------
#define KNN_INSERT(e, c)                                                     \
    if ((e) < mx) {                                                          \
        bool m0 = (bd[0] == mx), m1 = (bd[1] == mx);                         \
        bool m2 = (bd[2] == mx), m3 = (bd[3] == mx);                         \
        bool m4 = (bd[4] == mx), m5 = (bd[5] == mx);                         \
        bool m6 = (bd[6] == mx), m7 = (bd[7] == mx);                         \
        bool m8 = (bd[8] == mx), m9 = (bd[9] == mx);                         \
        bool o01 = m0 | m1, o23 = m2 | m3, o45 = m4 | m5, o67 = m6 | m7;     \
        bool o03 = o01 | o23, o07 = o03 | o45 | o67;                         \
        if (m0)                      { bd[0] = (e); bi[0] = (c); }           \
        if (m1 & !m0)                { bd[1] = (e); bi[1] = (c); }           \
        if (m2 & !o01)               { bd[2] = (e); bi[2] = (c); }           \
        if (m3 & !(o01 | m2))        { bd[3] = (e); bi[3] = (c); }           \
        if (m4 & !o03)               { bd[4] = (e); bi[4] = (c); }           \
        if (m5 & !(o03 | m4))        { bd[5] = (e); bi[5] = (c); }           \
        if (m6 & !(o03 | o45))       { bd[6] = (e); bi[6] = (c); }           \
        if (m7 & !(o03 | o45 | m6))  { bd[7] = (e); bi[7] = (c); }           \
        if (m8 & !o07)               { bd[8] = (e); bi[8] = (c); }           \
        if (m9 & !(o07 | m8))        { bd[9] = (e); bi[9] = (c); }           \
        float x0 = fmaxf(bd[0], bd[1]);                                      \
        float x1 = fmaxf(bd[2], bd[3]);                                      \
        float x2 = fmaxf(bd[4], bd[5]);                                      \
        float x3 = fmaxf(bd[6], bd[7]);                                      \
        float x4 = fmaxf(bd[8], bd[9]);                                      \
        mx = fmaxf(fmaxf(fmaxf(x0, x1), fmaxf(x2, x3)), x4);                 \
    }

// parallel-prefix 4-way append: independent predicated STS, 2-deep IADD tree
#define KNN_APPEND4(e0_, e1_, e2_, e3_, c0_, c1_, c2_, c3_)                  \
    {                                                                        \
        bool t0_ = (e0_) < mx, t1_ = (e1_) < mx;                             \
        bool t2_ = (e2_) < mx, t3_ = (e3_) < mx;                             \
        int s01_ = (int)t0_ + (int)t1_;                                      \
        int q0_ = cnt;                                                       \
        int q1_ = cnt + (int)t0_;                                            \
        int q2_ = cnt + s01_;                                                \
        int q3_ = q2_ + (int)t2_;                                            \
        if (t0_) sstk[q0_ * 1024 + tid] = make_float2((e0_), __int_as_float(c0_)); \
        if (t1_) sstk[q1_ * 1024 + tid] = make_float2((e1_), __int_as_float(c1_)); \
        if (t2_) sstk[q2_ * 1024 + tid] = make_float2((e2_), __int_as_float(c2_)); \
        if (t3_) sstk[q3_ * 1024 + tid] = make_float2((e3_), __int_as_float(c3_)); \
        cnt = q3_ + (int)t3_;                                                \
    }

// drain this thread's stack through the exact insert
#define KNN_DRAIN()                                                          \
    {                                                                        \
        for (int j = 0; j < cnt; ++j) {                                      \
            float2 v = sstk[j * 1024 + tid];                                 \
            float de = v.x;                                                  \
            int   dc = __float_as_int(v.y);                                  \
            KNN_INSERT(de, dc);                                              \
        }                                                                    \
        cnt = 0;                                                             \
    }

// evaluate 4 candidates (2 packed pairs at pair index pp) and append
#define KNN_EVAL4P(pp)                                                       \
    {                                                                        \
        ulonglong2 A0 = sptA[(pp)];                                          \
        ulonglong2 B0 = sptB[(pp)];                                          \
        ulonglong2 A1 = sptA[(pp) + 1];                                      \
        ulonglong2 B1 = sptB[(pp) + 1];                                      \
        unsigned long long u0_, u1_;                                         \
        FMA2(u0_, nqz2, B0.x, B0.y);                                         \
        FMA2(u0_, nqy2, A0.y, u0_);                                          \
        FMA2(u0_, nqx2, A0.x, u0_);                                          \
        FMA2(u1_, nqz2, B1.x, B1.y);                                         \
        FMA2(u1_, nqy2, A1.y, u1_);                                          \
        FMA2(u1_, nqx2, A1.x, u1_);                                          \
        float e0_, e1_, e2_, e3_;                                            \
        UNPACK2(e0_, e1_, u0_);                                              \
        UNPACK2(e2_, e3_, u1_);                                              \
        KNN_APPEND4(e0_, e1_, e2_, e3_,                                      \
                    2 * (pp), 2 * (pp) + 1, 2 * (pp) + 2, 2 * (pp) + 3);     \
    }

// ---------------------------------------------------------------------------
// Kernel 1: brute-force kNN. 1024-thread blocks, grid=128 (1 block/SM,
// 32 warps/SM = 8/SMSP). 4 threads per query, all in the SAME block: one
// point load, one shared buffer, 2x latency hiding. Pair-packed SMEM +
// f32x2 FMA, prefix appends, vote every 8, 12-deep stacks.
// Exact 4-way in-block merge; drop self (= global min).
// SMEM: A 32KB | B 32KB | stacks 96KB = 160KB
// ---------------------------------------------------------------------------
__global__ void __launch_bounds__(1024, 1) knn_kernel(const float* __restrict__ x)
{
    extern __shared__ char dsm[];
    ulonglong2* sptA = (ulonglong2*)dsm;             // 32 KB: 2048 pairs
    ulonglong2* sptB = (ulonglong2*)(dsm + 32768);   // 32 KB
    float2*     sstk = (float2*)(dsm + 65536);       // 96 KB: 12-deep stacks

    const int b  = blockIdx.x >> 4;              // 16 blocks per batch
    const int q0 = (blockIdx.x & 15) << 8;       // 256 queries per block
    const float* xb = x + b * 3 * NPTS;
    const int tid = threadIdx.x;

    {
        float* Af = (float*)dsm;
        float* Bf = (float*)(dsm + 32768);
        for (int i = tid; i < NPTS; i += 1024) {
            float px = xb[i];
            float py = xb[NPTS + i];
            float pz = xb[2 * NPTS + i];
            float pw = 0.5f * (px * px + py * py + pz * pz);
            int pi = i >> 1, lo = i & 1;
            Af[pi * 4 + lo]     = px;
            Af[pi * 4 + 2 + lo] = py;
            Bf[pi * 4 + lo]     = pz;
            Bf[pi * 4 + 2 + lo] = pw;
        }
    }
    __syncthreads();

    const int sub = tid >> 8;          // 0..3 : candidate quarter
    const int ql  = tid & 255;         // local query
    const int q   = q0 + ql;
    const int p0  = sub << 9;          // sub * 512 pairs (1024 candidates)

    // query coords from global (coalesced within warp)
    const float qx = xb[q], qy = xb[NPTS + q], qz = xb[2 * NPTS + q];
    unsigned long long nqx2, nqy2, nqz2;
    PACK2(nqx2, -qx, -qx);
    PACK2(nqy2, -qy, -qy);
    PACK2(nqz2, -qz, -qz);

    float bd[KN];
    int   bi[KN];
#pragma unroll
    for (int s = 0; s < KN; ++s) { bd[s] = INF_F; bi[s] = 0; }
    float mx = INF_F;
    int cnt = 0;

#pragma unroll 1
    for (int pp = p0; pp < p0 + 512; pp += 4) {   // 4 pairs = 8 candidates
        KNN_EVAL4P(pp);
        KNN_EVAL4P(pp + 2);
        if (__any_sync(0xffffffffu, cnt >= 5)) {
            KNN_DRAIN();
        }
    }
    KNN_DRAIN();

    // --- exact 4-way merge of partial lists (reuse stack region: 80KB) ---
    __syncthreads();
    float* pd = (float*)(dsm + 65536);               // 1024*10 floats = 40 KB
    int*   pi = (int*)(dsm + 65536 + 40960);         // 1024*10 ints   = 40 KB

    const int base = (ql * 4 + sub) * KN;
#pragma unroll
    for (int s = 0; s < KN; ++s) { pd[base + s] = bd[s]; pi[base + s] = bi[s]; }
    __syncthreads();

    if (sub == 0) {
#pragma unroll 1
        for (int t = 1; t < 4; ++t) {
            const int ob = (ql * 4 + t) * KN;
#pragma unroll
            for (int s = 0; s < KN; ++s) {
                float e = pd[ob + s];
                int   c = pi[ob + s];
                KNN_INSERT(e, c);
            }
        }

        // self = strict global min; emit the other 9 (order arbitrary)
        float mn = bd[0]; int ms = 0;
#pragma unroll
        for (int s = 1; s < KN; ++s) {
            if (bd[s] < mn) { mn = bd[s]; ms = s; }
        }
        int* outp = g_knn_idx + (b * NPTS + q) * NNB;
        int k = 0;
#pragma unroll
        for (int s = 0; s < KN; ++s) {
            if (s != ms) { outp[k] = bi[s]; ++k; }
        }
    }
}

// ---------------------------------------------------------------------------
// Kernel 2: umbrella features + fused MLP (BN folded). One thread per (b,n).
// (no reg cap: 255 regs, no spills — measured ~25us)
// ---------------------------------------------------------------------------
__global__ void __launch_bounds__(256) feat_kernel(
    const float* __restrict__ x,
    const float* __restrict__ conv1_w,
    const float* __restrict__ bn1_g, const float* __restrict__ bn1_b,
    const float* __restrict__ bn1_m, const float* __restrict__ bn1_v,
    const float* __restrict__ conv2_w, const float* __restrict__ conv2_b,
    const float* __restrict__ bn2_g, const float* __restrict__ bn2_b,
    const float* __restrict__ bn2_m, const float* __restrict__ bn2_v,
    const float* __restrict__ conv3_w, const float* __restrict__ conv3_b,
    float* __restrict__ out)
{
    extern __shared__ float4 spts[];
    __shared__ float W1f[81], W2f[81], W3s[81];
    __shared__ float b1f[9], b2f[9], b3f[9];

    const int b  = blockIdx.x >> 4;
    const int n0 = (blockIdx.x & 15) * 256;
    const int tid = threadIdx.x;

    if (tid < 81) {
        int o = tid / 9;
        float i1 = bn1_g[o] * rsqrtf(bn1_v[o] + 1e-5f);
        float i2 = bn2_g[o] * rsqrtf(bn2_v[o] + 1e-5f);
        W1f[tid] = conv1_w[tid] * i1;
        W2f[tid] = conv2_w[tid] * i2;
        W3s[tid] = conv3_w[tid];
        if (tid < 9) {
            float j1 = bn1_g[tid] * rsqrtf(bn1_v[tid] + 1e-5f);
            float j2 = bn2_g[tid] * rsqrtf(bn2_v[tid] + 1e-5f);
            b1f[tid] = bn1_b[tid] - bn1_m[tid] * j1;
            b2f[tid] = conv2_b[tid] * j2 + bn2_b[tid] - bn2_m[tid] * j2;
            b3f[tid] = conv3_b[tid];
        }
    }

    const float* xb = x + b * 3 * NPTS;
    for (int i = tid; i < NPTS; i += blockDim.x) {
        spts[i] = make_float4(xb[i], xb[NPTS + i], xb[2 * NPTS + i], 0.0f);
    }
    __syncthreads();

    const int n = n0 + tid;
    float4 p = spts[n];

    float gx[NNB], gy[NNB], gz[NNB], ph[NNB];
    const int* nb = g_knn_idx + (b * NPTS + n) * NNB;
#pragma unroll
    for (int j = 0; j < NNB; ++j) {
        float4 pp = spts[nb[j]];
        gx[j] = pp.x - p.x;
        gy[j] = pp.y - p.y;
        gz[j] = pp.z - p.z;
        ph[j] = atan2f(gy[j], gx[j]);
    }

#pragma unroll 1
    for (int a = 1; a < NNB; ++a) {
        float kp = ph[a], kx = gx[a], ky = gy[a], kz = gz[a];
        int t = a - 1;
        while (t >= 0 && ph[t] > kp) {
            ph[t + 1] = ph[t]; gx[t + 1] = gx[t]; gy[t + 1] = gy[t]; gz[t + 1] = gz[t];
            --t;
        }
        ph[t + 1] = kp; gx[t + 1] = kx; gy[t + 1] = ky; gz[t + 1] = kz;
    }

    float acc[9];
#pragma unroll
    for (int o = 0; o < 9; ++o) acc[o] = 0.0f;

    float pos = 1.0f;

#pragma unroll 1
    for (int j = 0; j < NNB; ++j) {
        int jn = (j + 1 == NNB) ? 0 : j + 1;
        float sx = gx[j],  sy = gy[j],  sz = gz[j];
        float rx = gx[jn], ry = gy[jn], rz = gz[jn];

        float cxv = sy * rz - sz * ry;
        float cyv = sz * rx - sx * rz;
        float czv = sx * ry - sy * rx;
        float nrm = sqrtf(cxv * cxv + cyv * cyv + czv * czv);
        float inn = 1.0f / fmaxf(nrm, 1e-10f);
        float ux = cxv * inn, uy = cyv * inn, uz = czv * inn;
        if (j == 0) pos = (ux > 0.0f) ? 1.0f : -1.0f;
        float nx = ux * pos, ny = uy * pos, nz = uz * pos;
        nx = isnan(nx) ? 0.0f : nx;
        ny = isnan(ny) ? 0.0f : ny;
        nz = isnan(nz) ? 0.0f : nz;

        float ccx = (sx + rx) * (1.0f / 3.0f);
        float ccy = (sy + ry) * (1.0f / 3.0f);
        float ccz = (sz + rz) * (1.0f / 3.0f);
        float rho = sqrtf(ccx * ccx + ccy * ccy + ccz * ccz);
        float ct  = ccz / fmaxf(rho, 1e-8f);
        ct = fminf(fmaxf(ct, -1.0f), 1.0f);
        float th  = acosf(ct) * (1.0f / PI_F);
        float phc = atan2f(ccy, ccx) * (1.0f / (2.0f * PI_F)) + 0.5f;

        float f[9] = { ccx, ccy, ccz, rho, th, phc, nx, ny, nz };

        float h1v[9];
#pragma unroll
        for (int o = 0; o < 9; ++o) {
            float a = b1f[o];
#pragma unroll
            for (int c = 0; c < 9; ++c) a = fmaf(W1f[o * 9 + c], f[c], a);
            h1v[o] = fmaxf(a, 0.0f);
        }
        float h2v[9];
#pragma unroll
        for (int o = 0; o < 9; ++o) {
            float a = b2f[o];
#pragma unroll
            for (int c = 0; c < 9; ++c) a = fmaf(W2f[o * 9 + c], h1v[c], a);
            h2v[o] = fmaxf(a, 0.0f);
        }
#pragma unroll
        for (int o = 0; o < 9; ++o) {
            float a = b3f[o];
#pragma unroll
            for (int c = 0; c < 9; ++c) a = fmaf(W3s[o * 9 + c], h2v[c], a);
            acc[o] += a;
        }
    }

    float* ob = out + b * 9 * NPTS + n;
#pragma unroll
    for (int o = 0; o < 9; ++o) ob[o * NPTS] = acc[o];
}

// ---------------------------------------------------------------------------
extern "C" void kernel_launch(void* const* d_in, const int* in_sizes, int n_in,
                              void* d_out, int out_size)
{
    const float* x       = (const float*)d_in[0];
    const float* conv1_w = (const float*)d_in[1];
    const float* bn1_g   = (const float*)d_in[2];
    const float* bn1_b   = (const float*)d_in[3];
    const float* bn1_m   = (const float*)d_in[4];
    const float* bn1_v   = (const float*)d_in[5];
    const float* conv2_w = (const float*)d_in[6];
    const float* conv2_b = (const float*)d_in[7];
    const float* bn2_g   = (const float*)d_in[8];
    const float* bn2_b   = (const float*)d_in[9];
    const float* bn2_m   = (const float*)d_in[10];
    const float* bn2_v   = (const float*)d_in[11];
    const float* conv3_w = (const float*)d_in[12];
    const float* conv3_b = (const float*)d_in[13];
    float* out = (float*)d_out;

    const int smem_knn  = 65536 + 98304;              // 160 KB
    const int smem_feat = NPTS * (int)sizeof(float4); // 64 KB
    cudaFuncSetAttribute(knn_kernel,  cudaFuncAttributeMaxDynamicSharedMemorySize, smem_knn);
    cudaFuncSetAttribute(feat_kernel, cudaFuncAttributeMaxDynamicSharedMemorySize, smem_feat);

    knn_kernel<<<BATCH * (NPTS / 256), 1024, smem_knn>>>(x);
    feat_kernel<<<BATCH * (NPTS / 256), 256, smem_feat>>>(
        x, conv1_w, bn1_g, bn1_b, bn1_m, bn1_v,
        conv2_w, conv2_b, bn2_g, bn2_b, bn2_m, bn2_v,
        conv3_w, conv3_b, out);
}

// round 16
// speedup vs baseline: 1.1511x; 1.1373x over previous
#include <cuda_runtime.h>
#include <math.h>
#include <float.h>

#define BATCH 8
#define NPTS  4096
#define KN    10
#define NNB   9
#define PI_F  3.14159265358979323846f
#define INF_F __int_as_float(0x7f800000)

// scratch: neighbor indices (B, N, 9)
__device__ int g_knn_idx[BATCH * NPTS * NNB];

// packed f32x2 fma (sm_103a): per-lane fp32 FMA, bit-identical to scalar fmaf
#define FMA2(out, a, b, c) \
    asm("fma.rn.f32x2 %0, %1, %2, %3;" : "=l"(out) : "l"(a), "l"(b), "l"(c))
#define UNPACK2(lo, hi, v) \
    asm("mov.b64 {%0, %1}, %2;" : "=f"(lo), "=f"(hi) : "l"(v))
#define PACK2(out, lo, hi) \
    asm("mov.b64 %0, {%1, %2};" : "=l"(out) : "f"(lo), "f"(hi))

// smem layout constants (knn)
#define PAIRS      2048
#define PAIRS_PAD  2050            // +2 pad pairs (w=+INF) for prefetch overrun
#define A_BYTES    32896           // 2050*16 rounded to 128
#define STK_BASE   (2 * A_BYTES)   // 65792
#define SMEM_KNN   (STK_BASE + 512 * 20 * 8)   // + 81920 = 147712

// ---------------------------------------------------------------------------
// insert: unsorted top-10, replace (first) slot equal to running max.
// parallel prefix-OR first-match + FMNMX tree. (proven exact, rounds 3-15)
// ---------------------------------------------------------------------------
#define KNN_INSERT(e, c)                                                     \
    if ((e) < mx) {                                                          \
        bool m0 = (bd[0] == mx), m1 = (bd[1] == mx);                         \
        bool m2 = (bd[2] == mx), m3 = (bd[3] == mx);                         \
        bool m4 = (bd[4] == mx), m5 = (bd[5] == mx);                         \
        bool m6 = (bd[6] == mx), m7 = (bd[7] == mx);                         \
        bool m8 = (bd[8] == mx), m9 = (bd[9] == mx);                         \
        bool o01 = m0 | m1, o23 = m2 | m3, o45 = m4 | m5, o67 = m6 | m7;     \
        bool o03 = o01 | o23, o07 = o03 | o45 | o67;                         \
        if (m0)                      { bd[0] = (e); bi[0] = (c); }           \
        if (m1 & !m0)                { bd[1] = (e); bi[1] = (c); }           \
        if (m2 & !o01)               { bd[2] = (e); bi[2] = (c); }           \
        if (m3 & !(o01 | m2))        { bd[3] = (e); bi[3] = (c); }           \
        if (m4 & !o03)               { bd[4] = (e); bi[4] = (c); }           \
        if (m5 & !(o03 | m4))        { bd[5] = (e); bi[5] = (c); }           \
        if (m6 & !(o03 | o45))       { bd[6] = (e); bi[6] = (c); }           \
        if (m7 & !(o03 | o45 | m6))  { bd[7] = (e); bi[7] = (c); }           \
        if (m8 & !o07)               { bd[8] = (e); bi[8] = (c); }           \
        if (m9 & !(o07 | m8))        { bd[9] = (e); bi[9] = (c); }           \
        float x0 = fmaxf(bd[0], bd[1]);                                      \
        float x1 = fmaxf(bd[2], bd[3]);                                      \
        float x2 = fmaxf(bd[4], bd[5]);                                      \
        float x3 = fmaxf(bd[6], bd[7]);                                      \
        float x4 = fmaxf(bd[8], bd[9]);                                      \
        mx = fmaxf(fmaxf(fmaxf(x0, x1), fmaxf(x2, x3)), x4);                 \
    }

// parallel-prefix 4-way append: independent predicated STS, 2-deep IADD tree
#define KNN_APPEND4(e0_, e1_, e2_, e3_, c0_, c1_, c2_, c3_)                  \
    {                                                                        \
        bool t0_ = (e0_) < mx, t1_ = (e1_) < mx;                             \
        bool t2_ = (e2_) < mx, t3_ = (e3_) < mx;                             \
        int s01_ = (int)t0_ + (int)t1_;                                      \
        int q0_ = cnt;                                                       \
        int q1_ = cnt + (int)t0_;                                            \
        int q2_ = cnt + s01_;                                                \
        int q3_ = q2_ + (int)t2_;                                            \
        if (t0_) sstk[q0_ * 512 + tid] = make_float2((e0_), __int_as_float(c0_)); \
        if (t1_) sstk[q1_ * 512 + tid] = make_float2((e1_), __int_as_float(c1_)); \
        if (t2_) sstk[q2_ * 512 + tid] = make_float2((e2_), __int_as_float(c2_)); \
        if (t3_) sstk[q3_ * 512 + tid] = make_float2((e3_), __int_as_float(c3_)); \
        cnt = q3_ + (int)t3_;                                                \
    }

// drain this thread's stack through the exact insert
#define KNN_DRAIN()                                                          \
    {                                                                        \
        for (int j = 0; j < cnt; ++j) {                                      \
            float2 v = sstk[j * 512 + tid];                                  \
            float de = v.x;                                                  \
            int   dc = __float_as_int(v.y);                                  \
            KNN_INSERT(de, dc);                                              \
        }                                                                    \
        cnt = 0;                                                             \
    }

// load 2 packed pairs (4 candidates) into register buffers
#define KNN_LOAD2(Aa, Ba, Ab, Bb, pp)                                        \
    { Aa = sptA[(pp)]; Ba = sptB[(pp)];                                      \
      Ab = sptA[(pp) + 1]; Bb = sptB[(pp) + 1]; }

// compute 4 candidates from preloaded registers and append
#define KNN_COMP4(Aa, Ba, Ab, Bb, ppi)                                       \
    {                                                                        \
        unsigned long long u0_, u1_;                                         \
        FMA2(u0_, nqz2, Ba.x, Ba.y);                                         \
        FMA2(u0_, nqy2, Aa.y, u0_);                                          \
        FMA2(u0_, nqx2, Aa.x, u0_);                                          \
        FMA2(u1_, nqz2, Bb.x, Bb.y);                                         \
        FMA2(u1_, nqy2, Ab.y, u1_);                                          \
        FMA2(u1_, nqx2, Ab.x, u1_);                                          \
        float e0_, e1_, e2_, e3_;                                            \
        UNPACK2(e0_, e1_, u0_);                                              \
        UNPACK2(e2_, e3_, u1_);                                              \
        KNN_APPEND4(e0_, e1_, e2_, e3_,                                      \
                    2 * (ppi), 2 * (ppi) + 1, 2 * (ppi) + 2, 2 * (ppi) + 3); \
    }

// ---------------------------------------------------------------------------
// Kernel 1: brute-force kNN. 2 threads per query (2048 candidates each),
// 512-thread blocks, grid=128 (1 block/SM). Pair-packed SMEM + f32x2 FMA,
// SOFTWARE-PIPELINED eval loop (double-buffered register prefetch hides LDS
// latency), prefix appends, vote every 16, 20-deep stacks. +INF pad pairs
// absorb the final prefetch overrun. Exact 2-way merge; drop self.
// ---------------------------------------------------------------------------
__global__ void __launch_bounds__(512) knn_kernel(const float* __restrict__ x)
{
    extern __shared__ char dsm[];
    ulonglong2* sptA = (ulonglong2*)dsm;                 // 2050 pairs
    ulonglong2* sptB = (ulonglong2*)(dsm + A_BYTES);     // 2050 pairs
    float2*     sstk = (float2*)(dsm + STK_BASE);        // 20-deep stacks

    const int b  = blockIdx.x >> 4;              // 16 blocks per batch
    const int q0 = (blockIdx.x & 15) << 8;       // 256 queries per block
    const float* xb = x + b * 3 * NPTS;
    const int tid = threadIdx.x;

    {
        float* Af = (float*)dsm;
        float* Bf = (float*)(dsm + A_BYTES);
        for (int i = tid; i < NPTS; i += 512) {
            float px = xb[i];
            float py = xb[NPTS + i];
            float pz = xb[2 * NPTS + i];
            float pw = 0.5f * (px * px + py * py + pz * pz);
            int pi = i >> 1, lo = i & 1;
            Af[pi * 4 + lo]     = px;
            Af[pi * 4 + 2 + lo] = py;
            Bf[pi * 4 + lo]     = pz;
            Bf[pi * 4 + 2 + lo] = pw;
        }
        if (tid == 0) {
            // pad pairs: x=y=z=0, w=+INF  =>  e = +INF, never appended
            for (int pi = PAIRS; pi < PAIRS_PAD; ++pi) {
                Af[pi * 4 + 0] = 0.0f; Af[pi * 4 + 1] = 0.0f;
                Af[pi * 4 + 2] = 0.0f; Af[pi * 4 + 3] = 0.0f;
                Bf[pi * 4 + 0] = 0.0f; Bf[pi * 4 + 1] = 0.0f;
                Bf[pi * 4 + 2] = INF_F; Bf[pi * 4 + 3] = INF_F;
            }
        }
    }
    __syncthreads();

    const int sub = tid >> 8;        // warps 0-7: sub 0, warps 8-15: sub 1
    const int ql  = tid & 255;
    const int q   = q0 + ql;
    const int p0  = sub << 10;       // sub * 1024 pairs (2048 candidates)

    // query coords from global (coalesced within warp)
    const float qx = xb[q], qy = xb[NPTS + q], qz = xb[2 * NPTS + q];
    unsigned long long nqx2, nqy2, nqz2;
    PACK2(nqx2, -qx, -qx);
    PACK2(nqy2, -qy, -qy);
    PACK2(nqz2, -qz, -qz);

    float bd[KN];
    int   bi[KN];
#pragma unroll
    for (int s = 0; s < KN; ++s) { bd[s] = INF_F; bi[s] = 0; }
    float mx = INF_F;
    int cnt = 0;

    // software-pipelined scan: buffers (a0,b0,a1,b1) / (a2,b2,a3,b3)
    ulonglong2 a0, b0, a1, b1, a2, b2, a3, b3;
    KNN_LOAD2(a0, b0, a1, b1, p0);

#pragma unroll 1
    for (int pp = p0; pp < p0 + 1024; pp += 8) {   // 8 pairs = 16 candidates
        KNN_LOAD2(a2, b2, a3, b3, pp + 2);
        KNN_COMP4(a0, b0, a1, b1, pp);
        KNN_LOAD2(a0, b0, a1, b1, pp + 4);
        KNN_COMP4(a2, b2, a3, b3, pp + 2);
        KNN_LOAD2(a2, b2, a3, b3, pp + 6);
        KNN_COMP4(a0, b0, a1, b1, pp + 4);
        KNN_LOAD2(a0, b0, a1, b1, pp + 8);   // prefetch next iter (pads at end)
        KNN_COMP4(a2, b2, a3, b3, pp + 6);
        if (__any_sync(0xffffffffu, cnt >= 5)) {
            KNN_DRAIN();
        }
    }
    KNN_DRAIN();

    // --- exact merge of the two partial lists (reuse point region) ---
    __syncthreads();
    float* pd = (float*)dsm;                    // 512*10 floats = 20 KB
    int*   pi = (int*)(pd + 512 * KN);          // 512*10 ints   = 20 KB

    const int base = (ql * 2 + sub) * KN;
#pragma unroll
    for (int s = 0; s < KN; ++s) { pd[base + s] = bd[s]; pi[base + s] = bi[s]; }
    __syncthreads();

    if (sub == 0) {
        const int ob = (ql * 2 + 1) * KN;
#pragma unroll
        for (int s = 0; s < KN; ++s) {
            float e = pd[ob + s];
            int   c = pi[ob + s];
            KNN_INSERT(e, c);
        }

        // self = strict global min; emit the other 9 (order arbitrary)
        float mn = bd[0]; int ms = 0;
#pragma unroll
        for (int s = 1; s < KN; ++s) {
            if (bd[s] < mn) { mn = bd[s]; ms = s; }
        }
        int* outp = g_knn_idx + (b * NPTS + q) * NNB;
        int k = 0;
#pragma unroll
        for (int s = 0; s < KN; ++s) {
            if (s != ms) { outp[k] = bi[s]; ++k; }
        }
    }
}

// ---------------------------------------------------------------------------
// Kernel 2: umbrella features + fused MLP (BN folded). One thread per (b,n).
// (no reg cap: 255 regs, no spills — measured ~25us)
// ---------------------------------------------------------------------------
__global__ void __launch_bounds__(256) feat_kernel(
    const float* __restrict__ x,
    const float* __restrict__ conv1_w,
    const float* __restrict__ bn1_g, const float* __restrict__ bn1_b,
    const float* __restrict__ bn1_m, const float* __restrict__ bn1_v,
    const float* __restrict__ conv2_w, const float* __restrict__ conv2_b,
    const float* __restrict__ bn2_g, const float* __restrict__ bn2_b,
    const float* __restrict__ bn2_m, const float* __restrict__ bn2_v,
    const float* __restrict__ conv3_w, const float* __restrict__ conv3_b,
    float* __restrict__ out)
{
    extern __shared__ float4 spts[];
    __shared__ float W1f[81], W2f[81], W3s[81];
    __shared__ float b1f[9], b2f[9], b3f[9];

    const int b  = blockIdx.x >> 4;
    const int n0 = (blockIdx.x & 15) * 256;
    const int tid = threadIdx.x;

    if (tid < 81) {
        int o = tid / 9;
        float i1 = bn1_g[o] * rsqrtf(bn1_v[o] + 1e-5f);
        float i2 = bn2_g[o] * rsqrtf(bn2_v[o] + 1e-5f);
        W1f[tid] = conv1_w[tid] * i1;
        W2f[tid] = conv2_w[tid] * i2;
        W3s[tid] = conv3_w[tid];
        if (tid < 9) {
            float j1 = bn1_g[tid] * rsqrtf(bn1_v[tid] + 1e-5f);
            float j2 = bn2_g[tid] * rsqrtf(bn2_v[tid] + 1e-5f);
            b1f[tid] = bn1_b[tid] - bn1_m[tid] * j1;
            b2f[tid] = conv2_b[tid] * j2 + bn2_b[tid] - bn2_m[tid] * j2;
            b3f[tid] = conv3_b[tid];
        }
    }

    const float* xb = x + b * 3 * NPTS;
    for (int i = tid; i < NPTS; i += blockDim.x) {
        spts[i] = make_float4(xb[i], xb[NPTS + i], xb[2 * NPTS + i], 0.0f);
    }
    __syncthreads();

    const int n = n0 + tid;
    float4 p = spts[n];

    float gx[NNB], gy[NNB], gz[NNB], ph[NNB];
    const int* nb = g_knn_idx + (b * NPTS + n) * NNB;
#pragma unroll
    for (int j = 0; j < NNB; ++j) {
        float4 pp = spts[nb[j]];
        gx[j] = pp.x - p.x;
        gy[j] = pp.y - p.y;
        gz[j] = pp.z - p.z;
        ph[j] = atan2f(gy[j], gx[j]);
    }

#pragma unroll 1
    for (int a = 1; a < NNB; ++a) {
        float kp = ph[a], kx = gx[a], ky = gy[a], kz = gz[a];
        int t = a - 1;
        while (t >= 0 && ph[t] > kp) {
            ph[t + 1] = ph[t]; gx[t + 1] = gx[t]; gy[t + 1] = gy[t]; gz[t + 1] = gz[t];
            --t;
        }
        ph[t + 1] = kp; gx[t + 1] = kx; gy[t + 1] = ky; gz[t + 1] = kz;
    }

    float acc[9];
#pragma unroll
    for (int o = 0; o < 9; ++o) acc[o] = 0.0f;

    float pos = 1.0f;

#pragma unroll 1
    for (int j = 0; j < NNB; ++j) {
        int jn = (j + 1 == NNB) ? 0 : j + 1;
        float sx = gx[j],  sy = gy[j],  sz = gz[j];
        float rx = gx[jn], ry = gy[jn], rz = gz[jn];

        float cxv = sy * rz - sz * ry;
        float cyv = sz * rx - sx * rz;
        float czv = sx * ry - sy * rx;
        float nrm = sqrtf(cxv * cxv + cyv * cyv + czv * czv);
        float inn = 1.0f / fmaxf(nrm, 1e-10f);
        float ux = cxv * inn, uy = cyv * inn, uz = czv * inn;
        if (j == 0) pos = (ux > 0.0f) ? 1.0f : -1.0f;
        float nx = ux * pos, ny = uy * pos, nz = uz * pos;
        nx = isnan(nx) ? 0.0f : nx;
        ny = isnan(ny) ? 0.0f : ny;
        nz = isnan(nz) ? 0.0f : nz;

        float ccx = (sx + rx) * (1.0f / 3.0f);
        float ccy = (sy + ry) * (1.0f / 3.0f);
        float ccz = (sz + rz) * (1.0f / 3.0f);
        float rho = sqrtf(ccx * ccx + ccy * ccy + ccz * ccz);
        float ct  = ccz / fmaxf(rho, 1e-8f);
        ct = fminf(fmaxf(ct, -1.0f), 1.0f);
        float th  = acosf(ct) * (1.0f / PI_F);
        float phc = atan2f(ccy, ccx) * (1.0f / (2.0f * PI_F)) + 0.5f;

        float f[9] = { ccx, ccy, ccz, rho, th, phc, nx, ny, nz };

        float h1v[9];
#pragma unroll
        for (int o = 0; o < 9; ++o) {
            float a = b1f[o];
#pragma unroll
            for (int c = 0; c < 9; ++c) a = fmaf(W1f[o * 9 + c], f[c], a);
            h1v[o] = fmaxf(a, 0.0f);
        }
        float h2v[9];
#pragma unroll
        for (int o = 0; o < 9; ++o) {
            float a = b2f[o];
#pragma unroll
            for (int c = 0; c < 9; ++c) a = fmaf(W2f[o * 9 + c], h1v[c], a);
            h2v[o] = fmaxf(a, 0.0f);
        }
#pragma unroll
        for (int o = 0; o < 9; ++o) {
            float a = b3f[o];
#pragma unroll
            for (int c = 0; c < 9; ++c) a = fmaf(W3s[o * 9 + c], h2v[c], a);
            acc[o] += a;
        }
    }

    float* ob = out + b * 9 * NPTS + n;
#pragma unroll
    for (int o = 0; o < 9; ++o) ob[o * NPTS] = acc[o];
}

// ---------------------------------------------------------------------------
extern "C" void kernel_launch(void* const* d_in, const int* in_sizes, int n_in,
                              void* d_out, int out_size)
{
    const float* x       = (const float*)d_in[0];
    const float* conv1_w = (const float*)d_in[1];
    const float* bn1_g   = (const float*)d_in[2];
    const float* bn1_b   = (const float*)d_in[3];
    const float* bn1_m   = (const float*)d_in[4];
    const float* bn1_v   = (const float*)d_in[5];
    const float* conv2_w = (const float*)d_in[6];
    const float* conv2_b = (const float*)d_in[7];
    const float* bn2_g   = (const float*)d_in[8];
    const float* bn2_b   = (const float*)d_in[9];
    const float* bn2_m   = (const float*)d_in[10];
    const float* bn2_v   = (const float*)d_in[11];
    const float* conv3_w = (const float*)d_in[12];
    const float* conv3_b = (const float*)d_in[13];
    float* out = (float*)d_out;

    const int smem_feat = NPTS * (int)sizeof(float4); // 64 KB
    cudaFuncSetAttribute(knn_kernel,  cudaFuncAttributeMaxDynamicSharedMemorySize, SMEM_KNN);
    cudaFuncSetAttribute(feat_kernel, cudaFuncAttributeMaxDynamicSharedMemorySize, smem_feat);

    knn_kernel<<<BATCH * (NPTS / 256), 512, SMEM_KNN>>>(x);
    feat_kernel<<<BATCH * (NPTS / 256), 256, smem_feat>>>(
        x, conv1_w, bn1_g, bn1_b, bn1_m, bn1_v,
        conv2_w, conv2_b, bn2_g, bn2_b, bn2_m, bn2_v,
        conv3_w, conv3_b, out);
}